// round 14
// baseline (speedup 1.0000x reference)
#include <cuda_runtime.h>
#include <cuda_fp16.h>
#include <cstdint>

#define NSEQ 512
#define CDIM 128
#define NN (NSEQ*NSEQ)

// scratch (all fp16)
__device__ __half g_bufA[(size_t)CDIM*NN];  // a[i,k,d] -> [d][i*512+k]
__device__ __half g_bufB[(size_t)CDIM*NN];  // b[k,j,d] -> [d][k*512+j]
// gate, channel-pair packed: gp[c>>1][ij][c&1]  (element = (c>>1)*2NN + 2*ij + (c&1))
__device__ __half g_bufG[(size_t)CDIM*NN];
__device__ __half g_bufX[(size_t)CDIM*NN];  // x -> [d][i*512+j]

// prepacked fp16 weights, m16n8k16 fragment order
__device__ uint4 g_wpA[5*2048];
__device__ uint2 g_wpB[4096];

// ---------------------------------------------------------------- helpers
__device__ __forceinline__ unsigned smem_u32(const void* p){
    return (unsigned)__cvta_generic_to_shared(p);
}
__device__ __forceinline__ unsigned h2u(float a, float b){
    __half2 h = __floats2half2_rn(a, b);
    return *(unsigned*)&h;
}
__device__ __forceinline__ void mma_f16(float c[4], const unsigned a[4], const unsigned b[2]){
    asm volatile("mma.sync.aligned.m16n8k16.row.col.f32.f16.f16.f32 "
        "{%0,%1,%2,%3}, {%4,%5,%6,%7}, {%8,%9}, {%0,%1,%2,%3};\n"
        : "+f"(c[0]),"+f"(c[1]),"+f"(c[2]),"+f"(c[3])
        : "r"(a[0]),"r"(a[1]),"r"(a[2]),"r"(a[3]), "r"(b[0]),"r"(b[1]));
}
__device__ __forceinline__ void ldmx4(unsigned r[4], unsigned addr){
    asm volatile("ldmatrix.sync.aligned.m8n8.x4.shared.b16 {%0,%1,%2,%3}, [%4];\n"
        : "=r"(r[0]),"=r"(r[1]),"=r"(r[2]),"=r"(r[3]) : "r"(addr));
}
__device__ __forceinline__ void ldmx2t(unsigned r[2], unsigned addr){
    asm volatile("ldmatrix.sync.aligned.m8n8.x2.trans.shared.b16 {%0,%1}, [%2];\n"
        : "=r"(r[0]),"=r"(r[1]) : "r"(addr));
}
__device__ __forceinline__ void cpa16(void* sdst, const void* gsrc){
    asm volatile("cp.async.cg.shared.global [%0], [%1], 16;\n"
        :: "r"(smem_u32(sdst)), "l"(gsrc));
}
__device__ __forceinline__ void cp_commit(){ asm volatile("cp.async.commit_group;\n"); }
template<int N> __device__ __forceinline__ void cp_wait(){
    asm volatile("cp.async.wait_group %0;\n" :: "n"(N));
}
__device__ __forceinline__ float sigmoidf_(float x){ return 1.f/(1.f+__expf(-x)); }
__device__ __forceinline__ unsigned US(const __half* p){ return *(const unsigned*)p; }

#define ZSTRIDE 136   // halves per smem row (128 data + 8 pad)

// ---------------------------------------------------------------------------
// Prepack: fp16 fragment-order weights (m16n8k16)
// ---------------------------------------------------------------------------
__global__ void __launch_bounds__(256) prepack_kernel(
    const float* __restrict__ agw, const float* __restrict__ apw,
    const float* __restrict__ bgw, const float* __restrict__ bpw,
    const float* __restrict__ gw,  const float* __restrict__ zw)
{
    int tid = blockIdx.x*256 + threadIdx.x;
    if (tid < 5*2048) {
        int m = tid >> 11, idx = tid & 2047;
        const float* W = (m==0)?agw:(m==1)?apw:(m==2)?bgw:(m==3)?bpw:gw;
        int lane = idx & 31, ks = (idx>>5) & 7, ct = idx >> 8;
        int g = lane>>2, tig = lane&3;
        const float* r0p = W + (size_t)(ct*16+g)*CDIM + ks*16 + tig*2;
        const float* r8p = r0p + 8*CDIM;
        uint4 v;
        v.x = h2u(r0p[0], r0p[1]);
        v.y = h2u(r8p[0], r8p[1]);
        v.z = h2u(r0p[8], r0p[9]);
        v.w = h2u(r8p[8], r8p[9]);
        g_wpA[tid] = v;
    } else if (tid < 5*2048 + 4096) {
        int idx = tid - 5*2048;
        int lane = idx & 31, ks = (idx>>5) & 7, j8 = idx >> 8;
        int g = lane>>2, tig = lane&3;
        const float* bp = zw + (size_t)(j8*8+g)*CDIM + ks*16 + tig*2;
        g_wpB[idx] = make_uint2(h2u(bp[0], bp[1]), h2u(bp[8], bp[9]));
    }
}

// ---------------------------------------------------------------------------
// Stage 1 (flipped GEMM, fp16): out[o][r] = W[o][:] . zn[r][:]
// 64 rows/block; warp w covers channels w*16..+15; gate split across 2 passes.
// Gate written channel-pair-packed via shfl exchange.
// ---------------------------------------------------------------------------
__global__ void __launch_bounds__(256,2) stage1_kernel(
    const float* __restrict__ z,   const float* __restrict__ mask,
    const float* __restrict__ lnw, const float* __restrict__ lnb,
    const float* __restrict__ agb, const float* __restrict__ apb,
    const float* __restrict__ bgb, const float* __restrict__ bpb,
    const float* __restrict__ gb)
{
    __shared__ __half s_zn[64*ZSTRIDE];   // [r][c]
    __shared__ float  s_msk[64];

    const int tid = threadIdx.x, lane = tid & 31, wid = tid >> 5;
    const int g = lane >> 2, tig = lane & 3;
    const int r0 = blockIdx.x * 64;

    if (tid < 64) s_msk[tid] = mask[r0 + tid];

    // LN: warp handles 8 rows; write fp16 zn
    {
        float4 wv = *(const float4*)(lnw + lane*4);
        float4 bv = *(const float4*)(lnb + lane*4);
        for (int it = 0; it < 8; ++it) {
            int row = wid*8 + it;
            float4 v = *(const float4*)(z + (size_t)(r0+row)*CDIM + lane*4);
            float s = v.x+v.y+v.z+v.w;
            #pragma unroll
            for (int o=16;o;o>>=1) s += __shfl_xor_sync(0xffffffffu, s, o);
            float mu = s * (1.f/CDIM);
            float dx=v.x-mu, dy=v.y-mu, dz=v.z-mu, dw=v.w-mu;
            float vv = dx*dx+dy*dy+dz*dz+dw*dw;
            #pragma unroll
            for (int o=16;o;o>>=1) vv += __shfl_xor_sync(0xffffffffu, vv, o);
            float rs = rsqrtf(vv*(1.f/CDIM) + 1e-5f);
            __half* dp = s_zn + row*ZSTRIDE + lane*4;
            *(unsigned*)(dp)     = h2u(dx*rs*wv.x+bv.x, dy*rs*wv.y+bv.y);
            *(unsigned*)(dp + 2) = h2u(dz*rs*wv.z+bv.z, dw*rs*wv.w+bv.w);
        }
    }
    __syncthreads();

    const int m0 = wid*16;
    const uint4* wbase = g_wpA + wid*256 + lane;   // [m][ct=wid][ks][lane]
    const float  bs0 = __ldg(gb+m0+g), bs8 = __ldg(gb+m0+g+8);

    #pragma unroll
    for (int ps = 0; ps < 2; ++ps) {
        const uint4* pG = wbase + (ps ? 2*2048 : 0);
        const uint4* pP = wbase + (ps ? 3*2048 : 1*2048);
        const uint4* pS = wbase + 4*2048;
        const float* b1v = ps ? bgb : agb;
        const float* b2v = ps ? bpb : apb;
        __half* dst = ps ? g_bufB : g_bufA;
        const int glo = ps*4;

        float accG[8][4], accP[8][4], accS[4][4];
        #pragma unroll
        for (int i=0;i<8;++i){
            #pragma unroll
            for (int j=0;j<4;++j){ accG[i][j]=0.f; accP[i][j]=0.f; }
        }
        #pragma unroll
        for (int i=0;i<4;++i){
            #pragma unroll
            for (int j=0;j<4;++j) accS[i][j]=0.f;
        }

        #pragma unroll 2
        for (int ks=0; ks<8; ++ks) {
            uint4 a1 = __ldg(pG + ks*32);
            uint4 a2 = __ldg(pP + ks*32);
            uint4 a3 = __ldg(pS + ks*32);
            #pragma unroll
            for (int nt=0; nt<8; ++nt) {
                const __half* bp = s_zn + (nt*8+g)*ZSTRIDE + ks*16 + 2*tig;
                unsigned b[2] = { US(bp), US(bp + 8) };
                mma_f16(accG[nt], (const unsigned*)&a1, b);
                mma_f16(accP[nt], (const unsigned*)&a2, b);
                if (nt >= glo && nt < glo+4)
                    mma_f16(accS[nt-glo], (const unsigned*)&a3, b);
            }
        }

        // pair epilogue: fp16( mask * sigmoid(G+b1) * (P+b2) ), d-major
        const float bG0 = __ldg(b1v+m0+g), bG8 = __ldg(b1v+m0+g+8);
        const float bP0 = __ldg(b2v+m0+g), bP8 = __ldg(b2v+m0+g+8);
        #pragma unroll
        for (int nt=0; nt<8; ++nt) {
            const int rr = nt*8 + tig*2;
            const float mk0 = s_msk[rr], mk1 = s_msk[rr+1];
            unsigned o0 = h2u(mk0 * sigmoidf_(accG[nt][0]+bG0) * (accP[nt][0]+bP0),
                              mk1 * sigmoidf_(accG[nt][1]+bG0) * (accP[nt][1]+bP0));
            unsigned o1 = h2u(mk0 * sigmoidf_(accG[nt][2]+bG8) * (accP[nt][2]+bP8),
                              mk1 * sigmoidf_(accG[nt][3]+bG8) * (accP[nt][3]+bP8));
            *(unsigned*)(dst + (size_t)(m0+g)*NN   + r0 + rr) = o0;
            *(unsigned*)(dst + (size_t)(m0+g+8)*NN + r0 + rr) = o1;
        }
        // gate epilogue, channel-pair packed:
        //   even-g thread writes pair (m0+g, m0+g+1); odd-g writes (m0+g+7, m0+g+8)
        #pragma unroll
        for (int nt2=0; nt2<4; ++nt2) {
            const int rr = (glo+nt2)*8 + tig*2;
            float s0 = sigmoidf_(accS[nt2][0]+bs0);   // (m0+g,   rr)
            float s1 = sigmoidf_(accS[nt2][1]+bs0);   // (m0+g,   rr+1)
            float s2 = sigmoidf_(accS[nt2][2]+bs8);   // (m0+g+8, rr)
            float s3 = sigmoidf_(accS[nt2][3]+bs8);   // (m0+g+8, rr+1)
            float t0 = __shfl_xor_sync(0xffffffffu, s0, 4);
            float t1 = __shfl_xor_sync(0xffffffffu, s1, 4);
            float t2 = __shfl_xor_sync(0xffffffffu, s2, 4);
            float t3 = __shfl_xor_sync(0xffffffffu, s3, 4);
            if ((g & 1) == 0) {
                // channels (m0+g, m0+g+1): partner (g+1) supplies s0/s1
                uint2 w = make_uint2(h2u(s0, t0), h2u(s1, t1));
                *(uint2*)(g_bufG + ((size_t)((m0+g)>>1))*(2*NN) + 2*(r0+rr)) = w;
            } else {
                // channels (m0+g+7, m0+g+8): partner (g-1) supplies its +8 values
                uint2 w = make_uint2(h2u(t2, s2), h2u(t3, s3));
                *(uint2*)(g_bufG + ((size_t)((m0+g+7)>>1))*(2*NN) + 2*(r0+rr)) = w;
            }
        }
    }
}

// ---------------------------------------------------------------------------
// Stage 2: per-d fp16 GEMM x[d] = a[d] @ b[d], fp16 out. 128x128 tile,
// kt=32, cp.async 2-buf, ldmatrix(+trans).
// ---------------------------------------------------------------------------
__global__ void __launch_bounds__(256,2) stage2_kernel()
{
    __shared__ __align__(16) __half As[2][128*40];   // [i][k], pad 40
    __shared__ __align__(16) __half Bs[2][32*136];   // [k][j], pad 136

    const int d = blockIdx.z;
    const __half* gA = g_bufA + (size_t)d*NN;
    const __half* gB = g_bufB + (size_t)d*NN;
    __half* gC = g_bufX + (size_t)d*NN;
    const int i0 = blockIdx.y*128, j0 = blockIdx.x*128;
    const int tid = threadIdx.x, lane = tid&31, wid = tid>>5;
    const int wm = wid & 3, wn = wid >> 2;    // 4x2 warp grid: 32 rows x 64 cols

    float acc[2][8][4];
    #pragma unroll
    for (int a=0;a<2;++a){
        #pragma unroll
        for(int b=0;b<8;++b){
            #pragma unroll
            for(int c=0;c<4;++c) acc[a][b][c]=0.f;
        }
    }

    auto load_tile = [&](int kt, int buf){
        #pragma unroll
        for (int i=0;i<2;++i){
            int cid = tid + i*256;
            int r = cid>>2, kc = (cid&3)*8;
            cpa16(&As[buf][r*40+kc], gA + (size_t)(i0+r)*NSEQ + kt + kc);
        }
        #pragma unroll
        for (int i=0;i<2;++i){
            int cid = tid + i*256;
            int kk = cid>>4, jc = (cid&15)*8;
            cpa16(&Bs[buf][kk*136+jc], gB + (size_t)(kt+kk)*NSEQ + j0 + jc);
        }
        cp_commit();
    };

    load_tile(0, 0);
    int buf = 0;
    for (int t=0; t<16; ++t) {
        if (t < 15) { load_tile((t+1)*32, buf^1); cp_wait<1>(); }
        else        { cp_wait<0>(); }
        __syncthreads();
        #pragma unroll
        for (int ks=0; ks<2; ++ks) {
            unsigned afr[2][4];
            #pragma unroll
            for (int mt=0; mt<2; ++mt)
                ldmx4(afr[mt], smem_u32(&As[buf][(wm*32 + mt*16 + (lane&15))*40
                                                 + ks*16 + (lane>>4)*8]));
            #pragma unroll
            for (int nt=0; nt<8; ++nt) {
                unsigned b[2];
                ldmx2t(b, smem_u32(&Bs[buf][(ks*16 + (lane&15))*136 + wn*64 + nt*8]));
                mma_f16(acc[0][nt], afr[0], b);
                mma_f16(acc[1][nt], afr[1], b);
            }
        }
        __syncthreads();
        buf ^= 1;
    }

    #pragma unroll
    for (int mt=0; mt<2; ++mt){
        #pragma unroll
        for (int nt=0; nt<8; ++nt) {
            int r = i0 + wm*32 + mt*16 + (lane>>2);
            int c = j0 + wn*64 + nt*8 + (lane&3)*2;
            *(unsigned*)(gC + (size_t)r*NSEQ + c)     = h2u(acc[mt][nt][0], acc[mt][nt][1]);
            *(unsigned*)(gC + (size_t)(r+8)*NSEQ + c) = h2u(acc[mt][nt][2], acc[mt][nt][3]);
        }
    }
}

// ---------------------------------------------------------------------------
// Stage 3: gather x (fp16), LN -> fp16, final projection (packed zw),
// gate multiplied straight from pair-packed global, store fp32. 64 rows/block.
// Warp w: rows m0=(w&3)*16, output cols n0=(w>>2)*64.
// ---------------------------------------------------------------------------
__global__ void __launch_bounds__(256,3) stage3_kernel(
    const float* __restrict__ lnow, const float* __restrict__ lnob,
    const float* __restrict__ zb,   float* __restrict__ out)
{
    extern __shared__ char smraw[];
    float*  s_x  = (float*)smraw;                 // [64][133]  x
    __half* s_xn = (__half*)(s_x + 64*133);       // [64][ZSTRIDE] fp16

    const int tid = threadIdx.x, lane = tid&31, wid = tid>>5;
    const int g = lane >> 2, tig = lane & 3;
    const int bi = blockIdx.x;
    const int ti = bi >> 3, j0 = (bi & 7)*64;
    const size_t rbase = (size_t)ti*NSEQ + j0;

    // gather x[d][rbase + rc] (fp16) -> s_x[r][d] (fp32)
    #pragma unroll
    for (int it=0; it<8; ++it){
        int cid = tid + it*256; int dd = cid>>4; int rc = (cid&15)*4;
        uint2 v = *(const uint2*)(g_bufX + (size_t)dd*NN + rbase + rc);
        __half2 h0 = *(__half2*)&v.x, h1 = *(__half2*)&v.y;
        s_x[(rc+0)*133 + dd] = __low2float(h0);
        s_x[(rc+1)*133 + dd] = __high2float(h0);
        s_x[(rc+2)*133 + dd] = __low2float(h1);
        s_x[(rc+3)*133 + dd] = __high2float(h1);
    }
    __syncthreads();

    // LN over d -> fp16
    {
        float4 wv = *(const float4*)(lnow + lane*4);
        float4 bv = *(const float4*)(lnob + lane*4);
        for (int it=0; it<8; ++it){
            int row = wid*8 + it;
            const float* rp = s_x + row*133 + lane*4;
            float e0=rp[0], e1=rp[1], e2=rp[2], e3=rp[3];
            float s = e0+e1+e2+e3;
            #pragma unroll
            for (int o=16;o;o>>=1) s += __shfl_xor_sync(0xffffffffu, s, o);
            float mu = s*(1.f/CDIM);
            float dx=e0-mu, dy=e1-mu, dz=e2-mu, dw=e3-mu;
            float vv = dx*dx+dy*dy+dz*dz+dw*dw;
            #pragma unroll
            for (int o=16;o;o>>=1) vv += __shfl_xor_sync(0xffffffffu, vv, o);
            float rs = rsqrtf(vv*(1.f/CDIM)+1e-5f);
            __half* dp = s_xn + row*ZSTRIDE + lane*4;
            *(unsigned*)(dp)     = h2u(dx*rs*wv.x+bv.x, dy*rs*wv.y+bv.y);
            *(unsigned*)(dp + 2) = h2u(dz*rs*wv.z+bv.z, dw*rs*wv.w+bv.w);
        }
    }
    __syncthreads();

    const int m0 = (wid&3)*16, n0 = (wid>>2)*64;
    float acc[8][4];
    #pragma unroll
    for (int i=0;i<8;++i){
        #pragma unroll
        for(int j=0;j<4;++j) acc[i][j]=0.f;
    }
    #pragma unroll 2
    for (int ks=0; ks<8; ++ks) {
        unsigned a[4];
        const __half* p0 = s_xn + (m0+g)*ZSTRIDE   + ks*16 + 2*tig;
        const __half* p1 = s_xn + (m0+g+8)*ZSTRIDE + ks*16 + 2*tig;
        a[0]=US(p0); a[1]=US(p1); a[2]=US(p0+8); a[3]=US(p1+8);
        #pragma unroll
        for (int nt=0; nt<8; ++nt) {
            uint2 bw = __ldg(g_wpB + ((n0>>3)+nt)*256 + ks*32 + lane);
            unsigned b[2] = { bw.x, bw.y };
            mma_f16(acc[nt], a, b);
        }
    }

    #pragma unroll
    for (int nt=0; nt<8; ++nt){
        const int o = n0 + nt*8 + tig*2;           // even channel
        const float zb0 = __ldg(zb+o), zb1 = __ldg(zb+o+1);
        const __half* gp = g_bufG + ((size_t)(o>>1))*(2*NN);
        {
            int r = m0 + g;
            unsigned gu = *(const unsigned*)(gp + 2*(rbase + r));
            __half2 gh = *(__half2*)&gu;
            float2 ov = make_float2((acc[nt][0]+zb0) * __low2float(gh),
                                    (acc[nt][1]+zb1) * __high2float(gh));
            *(float2*)(out + (rbase + r)*CDIM + o) = ov;
        }
        {
            int r = m0 + g + 8;
            unsigned gu = *(const unsigned*)(gp + 2*(rbase + r));
            __half2 gh = *(__half2*)&gu;
            float2 ov = make_float2((acc[nt][2]+zb0) * __low2float(gh),
                                    (acc[nt][3]+zb1) * __high2float(gh));
            *(float2*)(out + (rbase + r)*CDIM + o) = ov;
        }
    }
}

// ---------------------------------------------------------------------------
extern "C" void kernel_launch(void* const* d_in, const int* in_sizes, int n_in,
                              void* d_out, int out_size)
{
    const float* z    = (const float*)d_in[0];
    const float* mask = (const float*)d_in[1];
    const float* lniw = (const float*)d_in[2];
    const float* lnib = (const float*)d_in[3];
    const float* agw  = (const float*)d_in[4];
    const float* agb  = (const float*)d_in[5];
    const float* apw  = (const float*)d_in[6];
    const float* apb  = (const float*)d_in[7];
    const float* bgw  = (const float*)d_in[8];
    const float* bgb  = (const float*)d_in[9];
    const float* bpw  = (const float*)d_in[10];
    const float* bpb  = (const float*)d_in[11];
    const float* lnow = (const float*)d_in[12];
    const float* lnob = (const float*)d_in[13];
    const float* zw   = (const float*)d_in[14];
    const float* zb   = (const float*)d_in[15];
    const float* gww  = (const float*)d_in[16];
    const float* gwb  = (const float*)d_in[17];
    float* out = (float*)d_out;

    const int SMEM3 = 64*133*4 + 64*ZSTRIDE*2;     // ~51 KB
    cudaFuncSetAttribute(stage3_kernel, cudaFuncAttributeMaxDynamicSharedMemorySize, SMEM3);

    prepack_kernel<<<56, 256>>>(agw, apw, bgw, bpw, gww, zw);
    stage1_kernel<<<NN/64, 256>>>(z, mask, lniw, lnib,
                                  agb, apb, bgb, bpb, gwb);
    stage2_kernel<<<dim3(4,4,128), 256>>>();
    stage3_kernel<<<NN/64, 256, SMEM3>>>(lnow, lnob, zb, out);
}

// round 17
// speedup vs baseline: 1.0836x; 1.0836x over previous
#include <cuda_runtime.h>
#include <cuda_fp16.h>
#include <cstdint>

#define NSEQ 512
#define CDIM 128
#define NN (NSEQ*NSEQ)

// scratch (all fp16)
__device__ __half g_bufA[(size_t)CDIM*NN];  // a[i,k,d] -> [d][i*512+k]
__device__ __half g_bufB[(size_t)CDIM*NN];  // b[k,j,d] -> [d][k*512+j]
__device__ __half g_bufG[(size_t)CDIM*NN];  // gate     -> [d][i*512+j]
__device__ __half g_bufX[(size_t)CDIM*NN];  // x        -> [d][i*512+j]

// prepacked fp16 weights, m16n8k16 fragment order
__device__ uint4 g_wpA[5*2048];
__device__ uint2 g_wpB[4096];

// ---------------------------------------------------------------- helpers
__device__ __forceinline__ unsigned smem_u32(const void* p){
    return (unsigned)__cvta_generic_to_shared(p);
}
__device__ __forceinline__ unsigned h2u(float a, float b){
    __half2 h = __floats2half2_rn(a, b);
    return *(unsigned*)&h;
}
__device__ __forceinline__ void mma_f16(float c[4], const unsigned a[4], const unsigned b[2]){
    asm volatile("mma.sync.aligned.m16n8k16.row.col.f32.f16.f16.f32 "
        "{%0,%1,%2,%3}, {%4,%5,%6,%7}, {%8,%9}, {%0,%1,%2,%3};\n"
        : "+f"(c[0]),"+f"(c[1]),"+f"(c[2]),"+f"(c[3])
        : "r"(a[0]),"r"(a[1]),"r"(a[2]),"r"(a[3]), "r"(b[0]),"r"(b[1]));
}
__device__ __forceinline__ void ldmx4(unsigned r[4], unsigned addr){
    asm volatile("ldmatrix.sync.aligned.m8n8.x4.shared.b16 {%0,%1,%2,%3}, [%4];\n"
        : "=r"(r[0]),"=r"(r[1]),"=r"(r[2]),"=r"(r[3]) : "r"(addr));
}
__device__ __forceinline__ void ldmx2t(unsigned r[2], unsigned addr){
    asm volatile("ldmatrix.sync.aligned.m8n8.x2.trans.shared.b16 {%0,%1}, [%2];\n"
        : "=r"(r[0]),"=r"(r[1]) : "r"(addr));
}
__device__ __forceinline__ void cpa16(void* sdst, const void* gsrc){
    asm volatile("cp.async.cg.shared.global [%0], [%1], 16;\n"
        :: "r"(smem_u32(sdst)), "l"(gsrc));
}
__device__ __forceinline__ void cp_commit(){ asm volatile("cp.async.commit_group;\n"); }
template<int N> __device__ __forceinline__ void cp_wait(){
    asm volatile("cp.async.wait_group %0;\n" :: "n"(N));
}
__device__ __forceinline__ float sigmoidf_(float x){ return 1.f/(1.f+__expf(-x)); }
__device__ __forceinline__ unsigned US(const __half* p){ return *(const unsigned*)p; }

#define ZSTRIDE 136   // halves per smem row (128 data + 8 pad)

// ---------------------------------------------------------------------------
// Prepack: fp16 fragment-order weights (m16n8k16)
// ---------------------------------------------------------------------------
__global__ void __launch_bounds__(256) prepack_kernel(
    const float* __restrict__ agw, const float* __restrict__ apw,
    const float* __restrict__ bgw, const float* __restrict__ bpw,
    const float* __restrict__ gw,  const float* __restrict__ zw)
{
    int tid = blockIdx.x*256 + threadIdx.x;
    if (tid < 5*2048) {
        int m = tid >> 11, idx = tid & 2047;
        const float* W = (m==0)?agw:(m==1)?apw:(m==2)?bgw:(m==3)?bpw:gw;
        int lane = idx & 31, ks = (idx>>5) & 7, ct = idx >> 8;
        int g = lane>>2, tig = lane&3;
        const float* r0p = W + (size_t)(ct*16+g)*CDIM + ks*16 + tig*2;
        const float* r8p = r0p + 8*CDIM;
        uint4 v;
        v.x = h2u(r0p[0], r0p[1]);
        v.y = h2u(r8p[0], r8p[1]);
        v.z = h2u(r0p[8], r0p[9]);
        v.w = h2u(r8p[8], r8p[9]);
        g_wpA[tid] = v;
    } else if (tid < 5*2048 + 4096) {
        int idx = tid - 5*2048;
        int lane = idx & 31, ks = (idx>>5) & 7, j8 = idx >> 8;
        int g = lane>>2, tig = lane&3;
        const float* bp = zw + (size_t)(j8*8+g)*CDIM + ks*16 + tig*2;
        g_wpB[idx] = make_uint2(h2u(bp[0], bp[1]), h2u(bp[8], bp[9]));
    }
}

// ---------------------------------------------------------------------------
// Stage 1 (flipped GEMM, fp16): out[o][r] = W[o][:] . zn[r][:]
// 64 rows/block; warp w covers channels w*16..+15; gate split across 2 passes.
// ---------------------------------------------------------------------------
__global__ void __launch_bounds__(256,2) stage1_kernel(
    const float* __restrict__ z,   const float* __restrict__ mask,
    const float* __restrict__ lnw, const float* __restrict__ lnb,
    const float* __restrict__ agb, const float* __restrict__ apb,
    const float* __restrict__ bgb, const float* __restrict__ bpb,
    const float* __restrict__ gb)
{
    __shared__ __half s_zn[64*ZSTRIDE];   // [r][c]
    __shared__ float  s_msk[64];

    const int tid = threadIdx.x, lane = tid & 31, wid = tid >> 5;
    const int g = lane >> 2, tig = lane & 3;
    const int r0 = blockIdx.x * 64;

    if (tid < 64) s_msk[tid] = mask[r0 + tid];

    // LN: warp handles 8 rows; write fp16 zn
    {
        float4 wv = *(const float4*)(lnw + lane*4);
        float4 bv = *(const float4*)(lnb + lane*4);
        for (int it = 0; it < 8; ++it) {
            int row = wid*8 + it;
            float4 v = *(const float4*)(z + (size_t)(r0+row)*CDIM + lane*4);
            float s = v.x+v.y+v.z+v.w;
            #pragma unroll
            for (int o=16;o;o>>=1) s += __shfl_xor_sync(0xffffffffu, s, o);
            float mu = s * (1.f/CDIM);
            float dx=v.x-mu, dy=v.y-mu, dz=v.z-mu, dw=v.w-mu;
            float vv = dx*dx+dy*dy+dz*dz+dw*dw;
            #pragma unroll
            for (int o=16;o;o>>=1) vv += __shfl_xor_sync(0xffffffffu, vv, o);
            float rs = rsqrtf(vv*(1.f/CDIM) + 1e-5f);
            __half* dp = s_zn + row*ZSTRIDE + lane*4;
            *(unsigned*)(dp)     = h2u(dx*rs*wv.x+bv.x, dy*rs*wv.y+bv.y);
            *(unsigned*)(dp + 2) = h2u(dz*rs*wv.z+bv.z, dw*rs*wv.w+bv.w);
        }
    }
    __syncthreads();

    const int m0 = wid*16;
    const uint4* wbase = g_wpA + wid*256 + lane;   // [m][ct=wid][ks][lane]
    const float  bs0 = __ldg(gb+m0+g), bs8 = __ldg(gb+m0+g+8);

    #pragma unroll
    for (int ps = 0; ps < 2; ++ps) {
        const uint4* pG = wbase + (ps ? 2*2048 : 0);
        const uint4* pP = wbase + (ps ? 3*2048 : 1*2048);
        const uint4* pS = wbase + 4*2048;
        const float* b1v = ps ? bgb : agb;
        const float* b2v = ps ? bpb : apb;
        __half* dst = ps ? g_bufB : g_bufA;
        const int glo = ps*4;

        float accG[8][4], accP[8][4], accS[4][4];
        #pragma unroll
        for (int i=0;i<8;++i){
            #pragma unroll
            for (int j=0;j<4;++j){ accG[i][j]=0.f; accP[i][j]=0.f; }
        }
        #pragma unroll
        for (int i=0;i<4;++i){
            #pragma unroll
            for (int j=0;j<4;++j) accS[i][j]=0.f;
        }

        #pragma unroll 2
        for (int ks=0; ks<8; ++ks) {
            uint4 a1 = __ldg(pG + ks*32);
            uint4 a2 = __ldg(pP + ks*32);
            uint4 a3 = __ldg(pS + ks*32);
            #pragma unroll
            for (int nt=0; nt<8; ++nt) {
                const __half* bp = s_zn + (nt*8+g)*ZSTRIDE + ks*16 + 2*tig;
                unsigned b[2] = { US(bp), US(bp + 8) };
                mma_f16(accG[nt], (const unsigned*)&a1, b);
                mma_f16(accP[nt], (const unsigned*)&a2, b);
                if (nt >= glo && nt < glo+4)
                    mma_f16(accS[nt-glo], (const unsigned*)&a3, b);
            }
        }

        // pair epilogue: fp16( mask * sigmoid(G+b1) * (P+b2) ), d-major
        const float bG0 = __ldg(b1v+m0+g), bG8 = __ldg(b1v+m0+g+8);
        const float bP0 = __ldg(b2v+m0+g), bP8 = __ldg(b2v+m0+g+8);
        #pragma unroll
        for (int nt=0; nt<8; ++nt) {
            const int rr = nt*8 + tig*2;
            const float mk0 = s_msk[rr], mk1 = s_msk[rr+1];
            unsigned o0 = h2u(mk0 * sigmoidf_(accG[nt][0]+bG0) * (accP[nt][0]+bP0),
                              mk1 * sigmoidf_(accG[nt][1]+bG0) * (accP[nt][1]+bP0));
            unsigned o1 = h2u(mk0 * sigmoidf_(accG[nt][2]+bG8) * (accP[nt][2]+bP8),
                              mk1 * sigmoidf_(accG[nt][3]+bG8) * (accP[nt][3]+bP8));
            *(unsigned*)(dst + (size_t)(m0+g)*NN   + r0 + rr) = o0;
            *(unsigned*)(dst + (size_t)(m0+g+8)*NN + r0 + rr) = o1;
        }
        // gate epilogue (fp16), rows glo*8 .. glo*8+31
        #pragma unroll
        for (int nt2=0; nt2<4; ++nt2) {
            const int rr = (glo+nt2)*8 + tig*2;
            unsigned o0 = h2u(sigmoidf_(accS[nt2][0]+bs0), sigmoidf_(accS[nt2][1]+bs0));
            unsigned o1 = h2u(sigmoidf_(accS[nt2][2]+bs8), sigmoidf_(accS[nt2][3]+bs8));
            *(unsigned*)(g_bufG + (size_t)(m0+g)*NN   + r0 + rr) = o0;
            *(unsigned*)(g_bufG + (size_t)(m0+g+8)*NN + r0 + rr) = o1;
        }
    }
}

// ---------------------------------------------------------------------------
// Stage 2: per-d fp16 GEMM x[d] = a[d] @ b[d], fp16 out. 128x128 tile,
// kt=32, cp.async 3-stage pipeline (ONE syncthreads per K-tile), ldmatrix.
// ---------------------------------------------------------------------------
#define S2_AS 5120            // halves per A stage (128*40)
#define S2_BS 4352            // halves per B stage (32*136)
#define S2_STAGE (S2_AS + S2_BS)
#define S2_SMEM (3*S2_STAGE*2)

__global__ void __launch_bounds__(256,2) stage2_kernel()
{
    extern __shared__ __half sm2[];

    const int d = blockIdx.z;
    const __half* gA = g_bufA + (size_t)d*NN;
    const __half* gB = g_bufB + (size_t)d*NN;
    __half* gC = g_bufX + (size_t)d*NN;
    const int i0 = blockIdx.y*128, j0 = blockIdx.x*128;
    const int tid = threadIdx.x, lane = tid&31, wid = tid>>5;
    const int wm = wid & 3, wn = wid >> 2;    // 4x2 warp grid: 32 rows x 64 cols

    float acc[2][8][4];
    #pragma unroll
    for (int a=0;a<2;++a){
        #pragma unroll
        for(int b=0;b<8;++b){
            #pragma unroll
            for(int c=0;c<4;++c) acc[a][b][c]=0.f;
        }
    }

    auto load_tile = [&](int kt, int buf){
        __half* Ab = sm2 + buf*S2_STAGE;
        __half* Bb = Ab + S2_AS;
        #pragma unroll
        for (int i=0;i<2;++i){
            int cid = tid + i*256;
            int r = cid>>2, kc = (cid&3)*8;
            cpa16(Ab + r*40 + kc, gA + (size_t)(i0+r)*NSEQ + kt + kc);
        }
        #pragma unroll
        for (int i=0;i<2;++i){
            int cid = tid + i*256;
            int kk = cid>>4, jc = (cid&15)*8;
            cpa16(Bb + kk*136 + jc, gB + (size_t)(kt+kk)*NSEQ + j0 + jc);
        }
        cp_commit();
    };

    load_tile(0, 0);
    load_tile(32, 1);

    for (int t=0; t<16; ++t) {
        if (t < 15) cp_wait<1>(); else cp_wait<0>();
        __syncthreads();                       // all warps done computing t-1; tile t visible
        if (t+2 < 16) load_tile((t+2)*32, (t+2)%3);

        const int buf = t%3;
        const __half* Ab = sm2 + buf*S2_STAGE;
        const __half* Bb = Ab + S2_AS;
        #pragma unroll
        for (int ks=0; ks<2; ++ks) {
            unsigned afr[2][4];
            #pragma unroll
            for (int mt=0; mt<2; ++mt)
                ldmx4(afr[mt], smem_u32(Ab + (wm*32 + mt*16 + (lane&15))*40
                                           + ks*16 + (lane>>4)*8));
            #pragma unroll
            for (int nt=0; nt<8; ++nt) {
                unsigned b[2];
                ldmx2t(b, smem_u32(Bb + (ks*16 + (lane&15))*136 + wn*64 + nt*8));
                mma_f16(acc[0][nt], afr[0], b);
                mma_f16(acc[1][nt], afr[1], b);
            }
        }
    }

    #pragma unroll
    for (int mt=0; mt<2; ++mt){
        #pragma unroll
        for (int nt=0; nt<8; ++nt) {
            int r = i0 + wm*32 + mt*16 + (lane>>2);
            int c = j0 + wn*64 + nt*8 + (lane&3)*2;
            *(unsigned*)(gC + (size_t)r*NSEQ + c)     = h2u(acc[mt][nt][0], acc[mt][nt][1]);
            *(unsigned*)(gC + (size_t)(r+8)*NSEQ + c) = h2u(acc[mt][nt][2], acc[mt][nt][3]);
        }
    }
}

// ---------------------------------------------------------------------------
// Stage 3: gather x (fp16), LN -> fp16, final projection (packed zw),
// gate (fp16) multiply, store fp32. 64 rows/block, 3 CTAs/SM.
// Warp w: rows m0=(w&3)*16, output cols n0=(w>>2)*64.
// ---------------------------------------------------------------------------
__global__ void __launch_bounds__(256,3) stage3_kernel(
    const float* __restrict__ lnow, const float* __restrict__ lnob,
    const float* __restrict__ zb,   float* __restrict__ out)
{
    extern __shared__ char smraw[];
    float*  s_x  = (float*)smraw;                 // [64][133]  x, then gate
    __half* s_xn = (__half*)(s_x + 64*133);       // [64][ZSTRIDE] fp16

    const int tid = threadIdx.x, lane = tid&31, wid = tid>>5;
    const int g = lane >> 2, tig = lane & 3;
    const int bi = blockIdx.x;
    const int ti = bi >> 3, j0 = (bi & 7)*64;
    const size_t rbase = (size_t)ti*NSEQ + j0;

    // gather x[d][rbase + rc] (fp16) -> s_x[r][d] (fp32)
    #pragma unroll
    for (int it=0; it<8; ++it){
        int cid = tid + it*256; int dd = cid>>4; int rc = (cid&15)*4;
        uint2 v = *(const uint2*)(g_bufX + (size_t)dd*NN + rbase + rc);
        __half2 h0 = *(__half2*)&v.x, h1 = *(__half2*)&v.y;
        s_x[(rc+0)*133 + dd] = __low2float(h0);
        s_x[(rc+1)*133 + dd] = __high2float(h0);
        s_x[(rc+2)*133 + dd] = __low2float(h1);
        s_x[(rc+3)*133 + dd] = __high2float(h1);
    }
    __syncthreads();

    // LN over d -> fp16
    {
        float4 wv = *(const float4*)(lnow + lane*4);
        float4 bv = *(const float4*)(lnob + lane*4);
        for (int it=0; it<8; ++it){
            int row = wid*8 + it;
            const float* rp = s_x + row*133 + lane*4;
            float e0=rp[0], e1=rp[1], e2=rp[2], e3=rp[3];
            float s = e0+e1+e2+e3;
            #pragma unroll
            for (int o=16;o;o>>=1) s += __shfl_xor_sync(0xffffffffu, s, o);
            float mu = s*(1.f/CDIM);
            float dx=e0-mu, dy=e1-mu, dz=e2-mu, dw=e3-mu;
            float vv = dx*dx+dy*dy+dz*dz+dw*dw;
            #pragma unroll
            for (int o=16;o;o>>=1) vv += __shfl_xor_sync(0xffffffffu, vv, o);
            float rs = rsqrtf(vv*(1.f/CDIM)+1e-5f);
            __half* dp = s_xn + row*ZSTRIDE + lane*4;
            *(unsigned*)(dp)     = h2u(dx*rs*wv.x+bv.x, dy*rs*wv.y+bv.y);
            *(unsigned*)(dp + 2) = h2u(dz*rs*wv.z+bv.z, dw*rs*wv.w+bv.w);
        }
    }
    __syncthreads();

    // gate gather (fp16) overwrites s_x
    #pragma unroll
    for (int it=0; it<8; ++it){
        int cid = tid + it*256; int dd = cid>>4; int rc = (cid&15)*4;
        uint2 v = *(const uint2*)(g_bufG + (size_t)dd*NN + rbase + rc);
        __half2 h0 = *(__half2*)&v.x, h1 = *(__half2*)&v.y;
        s_x[(rc+0)*133 + dd] = __low2float(h0);
        s_x[(rc+1)*133 + dd] = __high2float(h0);
        s_x[(rc+2)*133 + dd] = __low2float(h1);
        s_x[(rc+3)*133 + dd] = __high2float(h1);
    }
    __syncthreads();

    const int m0 = (wid&3)*16, n0 = (wid>>2)*64;
    float acc[8][4];
    #pragma unroll
    for (int i=0;i<8;++i){
        #pragma unroll
        for(int j=0;j<4;++j) acc[i][j]=0.f;
    }
    #pragma unroll 2
    for (int ks=0; ks<8; ++ks) {
        unsigned a[4];
        const __half* p0 = s_xn + (m0+g)*ZSTRIDE   + ks*16 + 2*tig;
        const __half* p1 = s_xn + (m0+g+8)*ZSTRIDE + ks*16 + 2*tig;
        a[0]=US(p0); a[1]=US(p1); a[2]=US(p0+8); a[3]=US(p1+8);
        #pragma unroll
        for (int nt=0; nt<8; ++nt) {
            uint2 bw = __ldg(g_wpB + ((n0>>3)+nt)*256 + ks*32 + lane);
            unsigned b[2] = { bw.x, bw.y };
            mma_f16(acc[nt], a, b);
        }
    }

    #pragma unroll
    for (int nt=0; nt<8; ++nt){
        const int o = n0 + nt*8 + tig*2;
        const float zb0 = __ldg(zb+o), zb1 = __ldg(zb+o+1);
        {
            int r = m0 + g;
            float2 ov = make_float2((acc[nt][0]+zb0) * s_x[r*133+o],
                                    (acc[nt][1]+zb1) * s_x[r*133+o+1]);
            *(float2*)(out + (rbase + r)*CDIM + o) = ov;
        }
        {
            int r = m0 + g + 8;
            float2 ov = make_float2((acc[nt][2]+zb0) * s_x[r*133+o],
                                    (acc[nt][3]+zb1) * s_x[r*133+o+1]);
            *(float2*)(out + (rbase + r)*CDIM + o) = ov;
        }
    }
}

// ---------------------------------------------------------------------------
extern "C" void kernel_launch(void* const* d_in, const int* in_sizes, int n_in,
                              void* d_out, int out_size)
{
    const float* z    = (const float*)d_in[0];
    const float* mask = (const float*)d_in[1];
    const float* lniw = (const float*)d_in[2];
    const float* lnib = (const float*)d_in[3];
    const float* agw  = (const float*)d_in[4];
    const float* agb  = (const float*)d_in[5];
    const float* apw  = (const float*)d_in[6];
    const float* apb  = (const float*)d_in[7];
    const float* bgw  = (const float*)d_in[8];
    const float* bgb  = (const float*)d_in[9];
    const float* bpw  = (const float*)d_in[10];
    const float* bpb  = (const float*)d_in[11];
    const float* lnow = (const float*)d_in[12];
    const float* lnob = (const float*)d_in[13];
    const float* zw   = (const float*)d_in[14];
    const float* zb   = (const float*)d_in[15];
    const float* gww  = (const float*)d_in[16];
    const float* gwb  = (const float*)d_in[17];
    float* out = (float*)d_out;

    const int SMEM3 = 64*133*4 + 64*ZSTRIDE*2;     // ~51 KB
    cudaFuncSetAttribute(stage2_kernel, cudaFuncAttributeMaxDynamicSharedMemorySize, S2_SMEM);
    cudaFuncSetAttribute(stage3_kernel, cudaFuncAttributeMaxDynamicSharedMemorySize, SMEM3);

    prepack_kernel<<<56, 256>>>(agw, apw, bgw, bpw, gww, zw);
    stage1_kernel<<<NN/64, 256>>>(z, mask, lniw, lnib,
                                  agb, apb, bgb, bpb, gwb);
    stage2_kernel<<<dim3(4,4,128), 256, S2_SMEM>>>();
    stage3_kernel<<<NN/64, 256, SMEM3>>>(lnow, lnob, zb, out);
}